// round 1
// baseline (speedup 1.0000x reference)
#include <cuda_runtime.h>
#include <cuda_bf16.h>
#include <math.h>

// ---------------- problem constants ----------------
#define G        160
#define V        (G*G*G)          // 4,096,000 voxels
#define NRAYS    4096
#define S        256
#define NS       (NRAYS*S)        // 1,048,576 samples
#define C0CH     12               // k0 channels
#define DIM0     39               // 12 + 3 + 12 + 12
#define W        128
#define TILE     128              // samples per MLP block
#define ACT_SHIFT (-4.5951198501345898f)   // log(0.01/0.99)

// ---------------- scratch (device globals; no allocation allowed) ----------
__device__ float g_inter[(size_t)V * 16];   // [vox][16]: ch0..11 = k0, ch12 = density, 13..15 = 0
__device__ float g_sp[NS];                  // softplus(dens + shift)
__device__ float g_rgb[(size_t)NS * 3];     // per-sample rgb (post-sigmoid)

// ---------------- f32x2 helpers ----------------
__device__ __forceinline__ unsigned long long pack2(float x, float y) {
    unsigned long long r;
    asm("mov.b64 %0, {%1, %2};" : "=l"(r) : "f"(x), "f"(y));
    return r;
}
__device__ __forceinline__ void unpack2(unsigned long long v, float& lo, float& hi) {
    asm("mov.b64 {%0, %1}, %2;" : "=f"(lo), "=f"(hi) : "l"(v));
}
__device__ __forceinline__ void fma2(unsigned long long& d, unsigned long long a, unsigned long long b) {
    asm("fma.rn.f32x2 %0, %1, %2, %0;" : "+l"(d) : "l"(a), "l"(b));
}

// ---------------- kernel 1: transpose grids to interleaved layout ----------
// 32 voxels per block, 512 threads. Coalesced reads per-channel, coalesced
// interleaved writes via smem staging.
__global__ void k_transpose(const float* __restrict__ dens,
                            const float* __restrict__ k0) {
    __shared__ float s[13][33];
    int v0 = blockIdx.x * 32;
    int t = threadIdx.x;
    if (t < 13 * 32) {
        int c = t >> 5, v = t & 31;
        float val = (c < 12) ? k0[(size_t)c * V + v0 + v] : dens[v0 + v];
        s[c][v] = val;
    }
    __syncthreads();
    {   // 512 = 32 voxels * 16 channels, fully coalesced write
        int v = t >> 4, c = t & 15;
        g_inter[(size_t)(v0 + v) * 16 + c] = (c < 13) ? s[c][v] : 0.0f;
    }
}

// ---------------- kernel 2: featurize + MLP ----------------
// One block = 128 samples, 256 threads.
// smem layout (floats):
#define OFF_W1   0
#define OFF_H1   (OFF_W1 + 128*128)          // 16384
#define OFF_FEAT (OFF_H1 + 128*129)          // +16512
#define OFF_W0   (OFF_FEAT + 128*41)         // +5248
#define OFF_B0   (OFF_W0 + 39*128)           // +4992
#define OFF_B1   (OFF_B0 + 128)
#define OFF_W2   (OFF_B1 + 128)
#define OFF_B2   (OFF_W2 + 128*3)
#define OFF_RGBA (OFF_B2 + 4)
#define SMEM_FLOATS (OFF_RGBA + 128*3)
#define SMEM_BYTES (SMEM_FLOATS * 4)

__global__ __launch_bounds__(256, 1)
void k_mlp(const float* __restrict__ pts,
           const float* __restrict__ viewdirs,
           const float* __restrict__ w0g, const float* __restrict__ b0g,
           const float* __restrict__ w1g, const float* __restrict__ b1g,
           const float* __restrict__ w2g, const float* __restrict__ b2g) {
    extern __shared__ float sm[];
    float* w1s   = sm + OFF_W1;
    float* h1s   = sm + OFF_H1;
    float* feats = sm + OFF_FEAT;
    float* w0s   = sm + OFF_W0;
    float* b0s   = sm + OFF_B0;
    float* b1s   = sm + OFF_B1;
    float* w2s   = sm + OFF_W2;
    float* rgba  = sm + OFF_RGBA;

    const int t = threadIdx.x;
    const int blk = blockIdx.x;

    // ---- load weights into smem ----
    for (int i = t; i < 39 * 128; i += 256) w0s[i] = w0g[i];
    for (int i = t; i < 128 * 128; i += 256) w1s[i] = w1g[i];
    for (int i = t; i < 128 * 3; i += 256) w2s[i] = w2g[i];
    if (t < 128) { b0s[t] = b0g[t]; b1s[t] = b1g[t]; }
    // rgb accumulator init = b2
    for (int i = t; i < 128 * 3; i += 256) rgba[i] = b2g[i % 3];

    // ---- per-sample featurize (threads 0..127) ----
    if (t < 128) {
        int gs = blk * TILE + t;           // global sample
        int ray = gs >> 8;

        const float* pp = pts + (size_t)gs * 3;
        float f[3]; int i0[3];
        #pragma unroll
        for (int d = 0; d < 3; d++) {
            float u = (pp[d] + 1.0f) * (0.5f * (G - 1));
            u = fminf(fmaxf(u, 0.0f), (float)(G - 1));
            int ii = (int)floorf(u);
            ii = min(ii, G - 2);
            f[d] = u - (float)ii;
            i0[d] = ii;
        }
        float wx[2] = {1.0f - f[0], f[0]};
        float wy[2] = {1.0f - f[1], f[1]};
        float wz[2] = {1.0f - f[2], f[2]};

        float acc[13];
        #pragma unroll
        for (int c = 0; c < 13; c++) acc[c] = 0.0f;

        #pragma unroll
        for (int dx = 0; dx < 2; dx++)
        #pragma unroll
        for (int dy = 0; dy < 2; dy++)
        #pragma unroll
        for (int dz = 0; dz < 2; dz++) {
            float wgt = wx[dx] * wy[dy] * wz[dz];
            int vox = ((i0[0] + dx) * G + (i0[1] + dy)) * G + (i0[2] + dz);
            const float4* cp = reinterpret_cast<const float4*>(g_inter) + (size_t)vox * 4;
            float4 A = cp[0], B = cp[1], Cc = cp[2], D = cp[3];
            acc[0]  += wgt * A.x;  acc[1]  += wgt * A.y;
            acc[2]  += wgt * A.z;  acc[3]  += wgt * A.w;
            acc[4]  += wgt * B.x;  acc[5]  += wgt * B.y;
            acc[6]  += wgt * B.z;  acc[7]  += wgt * B.w;
            acc[8]  += wgt * Cc.x; acc[9]  += wgt * Cc.y;
            acc[10] += wgt * Cc.z; acc[11] += wgt * Cc.w;
            acc[12] += wgt * D.x;
        }

        // density -> softplus, stored for compositing
        float dd = acc[12] + ACT_SHIFT;
        float spv = (dd > 15.0f) ? dd : log1pf(expf(dd));
        g_sp[gs] = spv;

        // view embedding
        float vx = viewdirs[ray * 3 + 0];
        float vy = viewdirs[ray * 3 + 1];
        float vz = viewdirs[ray * 3 + 2];
        float inv = rsqrtf(vx * vx + vy * vy + vz * vz);
        vx *= inv; vy *= inv; vz *= inv;

        float* fr = feats + t * 41;
        #pragma unroll
        for (int c = 0; c < 12; c++) fr[c] = acc[c];
        fr[12] = vx; fr[13] = vy; fr[14] = vz;
        float vdn[3] = {vx, vy, vz};
        #pragma unroll
        for (int d = 0; d < 3; d++) {
            #pragma unroll
            for (int fq = 0; fq < 4; fq++) {
                float ang = vdn[d] * (float)(1 << fq);
                float sv, cv;
                sincosf(ang, &sv, &cv);
                fr[15 + d * 4 + fq] = sv;
                fr[27 + d * 4 + fq] = cv;
            }
        }
    }
    __syncthreads();

    // ---- thread tile mapping: 4 rows (rt+32i) x 16 cols (ct*16..) ----
    const int rt = t & 31;
    const int ct = t >> 5;
    const int c0 = ct * 16;

    unsigned long long accp[4][8];

    // ===== GEMM1: h1 = relu(feat @ w0 + b0), K=39 =====
    {
        const ulonglong2* bp = reinterpret_cast<const ulonglong2*>(b0s + c0);
        ulonglong2 q0 = bp[0], q1 = bp[1], q2 = bp[2], q3 = bp[3];
        #pragma unroll
        for (int i = 0; i < 4; i++) {
            accp[i][0] = q0.x; accp[i][1] = q0.y;
            accp[i][2] = q1.x; accp[i][3] = q1.y;
            accp[i][4] = q2.x; accp[i][5] = q2.y;
            accp[i][6] = q3.x; accp[i][7] = q3.y;
        }
        for (int k = 0; k < 39; k++) {
            unsigned long long ap[4];
            #pragma unroll
            for (int i = 0; i < 4; i++) {
                float a = feats[(rt + 32 * i) * 41 + k];
                ap[i] = pack2(a, a);
            }
            const ulonglong2* wp = reinterpret_cast<const ulonglong2*>(w0s + k * 128 + c0);
            ulonglong2 wa = wp[0], wb = wp[1], wc = wp[2], wd = wp[3];
            unsigned long long wv[8] = {wa.x, wa.y, wb.x, wb.y, wc.x, wc.y, wd.x, wd.y};
            #pragma unroll
            for (int i = 0; i < 4; i++)
                #pragma unroll
                for (int j = 0; j < 8; j++)
                    fma2(accp[i][j], ap[i], wv[j]);
        }
        #pragma unroll
        for (int i = 0; i < 4; i++) {
            int base = (rt + 32 * i) * 129 + c0;
            #pragma unroll
            for (int j = 0; j < 8; j++) {
                float lo, hi;
                unpack2(accp[i][j], lo, hi);
                h1s[base + 2 * j]     = fmaxf(lo, 0.0f);
                h1s[base + 2 * j + 1] = fmaxf(hi, 0.0f);
            }
        }
    }
    __syncthreads();

    // ===== GEMM2: h2 = relu(h1 @ w1 + b1), K=128; fused GEMM3 epilogue =====
    {
        const ulonglong2* bp = reinterpret_cast<const ulonglong2*>(b1s + c0);
        ulonglong2 q0 = bp[0], q1 = bp[1], q2 = bp[2], q3 = bp[3];
        #pragma unroll
        for (int i = 0; i < 4; i++) {
            accp[i][0] = q0.x; accp[i][1] = q0.y;
            accp[i][2] = q1.x; accp[i][3] = q1.y;
            accp[i][4] = q2.x; accp[i][5] = q2.y;
            accp[i][6] = q3.x; accp[i][7] = q3.y;
        }
        for (int k = 0; k < 128; k++) {
            unsigned long long ap[4];
            #pragma unroll
            for (int i = 0; i < 4; i++) {
                float a = h1s[(rt + 32 * i) * 129 + k];
                ap[i] = pack2(a, a);
            }
            const ulonglong2* wp = reinterpret_cast<const ulonglong2*>(w1s + k * 128 + c0);
            ulonglong2 wa = wp[0], wb = wp[1], wc = wp[2], wd = wp[3];
            unsigned long long wv[8] = {wa.x, wa.y, wb.x, wb.y, wc.x, wc.y, wd.x, wd.y};
            #pragma unroll
            for (int i = 0; i < 4; i++)
                #pragma unroll
                for (int j = 0; j < 8; j++)
                    fma2(accp[i][j], ap[i], wv[j]);
        }
        // epilogue: relu then partial h2 @ w2 into smem accumulator
        #pragma unroll
        for (int i = 0; i < 4; i++) {
            int r = rt + 32 * i;
            float p0 = 0.0f, p1 = 0.0f, p2 = 0.0f;
            #pragma unroll
            for (int j = 0; j < 8; j++) {
                float lo, hi;
                unpack2(accp[i][j], lo, hi);
                lo = fmaxf(lo, 0.0f);
                hi = fmaxf(hi, 0.0f);
                int col = c0 + 2 * j;
                p0 += lo * w2s[col * 3 + 0] + hi * w2s[(col + 1) * 3 + 0];
                p1 += lo * w2s[col * 3 + 1] + hi * w2s[(col + 1) * 3 + 1];
                p2 += lo * w2s[col * 3 + 2] + hi * w2s[(col + 1) * 3 + 2];
            }
            atomicAdd(&rgba[r * 3 + 0], p0);
            atomicAdd(&rgba[r * 3 + 1], p1);
            atomicAdd(&rgba[r * 3 + 2], p2);
        }
    }
    __syncthreads();

    // ---- sigmoid + store per-sample rgb ----
    if (t < 128) {
        int gs = blk * TILE + t;
        #pragma unroll
        for (int c = 0; c < 3; c++) {
            float x = rgba[t * 3 + c];
            g_rgb[(size_t)gs * 3 + c] = 1.0f / (1.0f + expf(-x));
        }
    }
}

// ---------------- kernel 3: per-ray composite ----------------
// T = cumprod(1-alpha) = exp(-0.5 * cumsum(softplus)); scan + reduce per ray.
__global__ void k_compose(float* __restrict__ out) {
    __shared__ float s_scan[256];
    __shared__ float s_r[256], s_g[256], s_b[256];
    int ray = blockIdx.x;
    int t = threadIdx.x;
    int gs = ray * 256 + t;

    float q = 0.5f * g_sp[gs];        // INTERVAL = 0.5
    s_scan[t] = q;
    __syncthreads();
    #pragma unroll
    for (int off = 1; off < 256; off <<= 1) {
        float v = (t >= off) ? s_scan[t - off] : 0.0f;
        __syncthreads();
        s_scan[t] += v;
        __syncthreads();
    }
    float incl = s_scan[t];
    float T_excl = expf(-(incl - q));
    float alpha = 1.0f - expf(-q);
    float wgt = alpha * T_excl;

    s_r[t] = wgt * g_rgb[(size_t)gs * 3 + 0];
    s_g[t] = wgt * g_rgb[(size_t)gs * 3 + 1];
    s_b[t] = wgt * g_rgb[(size_t)gs * 3 + 2];
    __syncthreads();
    for (int off = 128; off > 0; off >>= 1) {
        if (t < off) {
            s_r[t] += s_r[t + off];
            s_g[t] += s_g[t + off];
            s_b[t] += s_b[t + off];
        }
        __syncthreads();
    }
    if (t == 0) {
        float ainv = expf(-s_scan[255]);
        out[ray * 3 + 0] = s_r[0] + ainv;
        out[ray * 3 + 1] = s_g[0] + ainv;
        out[ray * 3 + 2] = s_b[0] + ainv;
    }
}

// ---------------- launch ----------------
extern "C" void kernel_launch(void* const* d_in, const int* in_sizes, int n_in,
                              void* d_out, int out_size) {
    const float* pts      = (const float*)d_in[0];
    const float* viewdirs = (const float*)d_in[1];
    const float* dens     = (const float*)d_in[2];
    const float* k0       = (const float*)d_in[3];
    const float* w0g      = (const float*)d_in[4];
    const float* b0g      = (const float*)d_in[5];
    const float* w1g      = (const float*)d_in[6];
    const float* b1g      = (const float*)d_in[7];
    const float* w2g      = (const float*)d_in[8];
    const float* b2g      = (const float*)d_in[9];
    float* out = (float*)d_out;

    cudaFuncSetAttribute(k_mlp, cudaFuncAttributeMaxDynamicSharedMemorySize, SMEM_BYTES);

    k_transpose<<<V / 32, 512>>>(dens, k0);
    k_mlp<<<NS / TILE, 256, SMEM_BYTES>>>(pts, viewdirs, w0g, b0g, w1g, b1g, w2g, b2g);
    k_compose<<<NRAYS, 256>>>(out);
}